// round 9
// baseline (speedup 1.0000x reference)
#include <cuda_runtime.h>
#include <cuda_fp16.h>
#include <cstdint>
#include <math.h>

#define B_SZ   8192
#define LEADS  12
#define FIN    512
#define HID    256
#define E3     768
#define MROWS  (B_SZ * LEADS)   // 98304

// ---------------- static scratch ----------------
__device__ float g_A[LEADS * LEADS];
__device__ __half g_qkv[(size_t)MROWS * E3];   // also reused as x16 before qkv
__device__ __half g_buf1[(size_t)MROWS * HID];
__device__ __half g_buf2[(size_t)MROWS * HID];
__device__ __half g_buf3[(size_t)MROWS * HID];

__device__ __half g_W1[HID * FIN];
__device__ __half g_W2[HID * HID];
__device__ __half g_W3[HID * HID];
__device__ __half g_Iw[E3 * HID];
__device__ __half g_Ow[HID * HID];

// ---------------- helpers ----------------
__device__ __forceinline__ uint32_t smem_u32(const void* p) {
    uint32_t a;
    asm("{ .reg .u64 t; cvta.to.shared.u64 t, %1; cvt.u32.u64 %0, t; }" : "=r"(a) : "l"(p));
    return a;
}
__device__ __forceinline__ void ldsm4(uint32_t& r0, uint32_t& r1, uint32_t& r2, uint32_t& r3,
                                      uint32_t a) {
    asm volatile("ldmatrix.sync.aligned.m8n8.x4.shared.b16 {%0,%1,%2,%3}, [%4];"
                 : "=r"(r0), "=r"(r1), "=r"(r2), "=r"(r3) : "r"(a));
}
__device__ __forceinline__ void mma16816(float* c, const uint32_t* a, const uint32_t* b) {
    asm volatile("mma.sync.aligned.m16n8k16.row.col.f32.f16.f16.f32 "
                 "{%0,%1,%2,%3}, {%4,%5,%6,%7}, {%8,%9}, {%0,%1,%2,%3};"
                 : "+f"(c[0]), "+f"(c[1]), "+f"(c[2]), "+f"(c[3])
                 : "r"(a[0]), "r"(a[1]), "r"(a[2]), "r"(a[3]), "r"(b[0]), "r"(b[1]));
}
__device__ __forceinline__ void cp16(uint32_t d, const void* g) {
    asm volatile("cp.async.ca.shared.global [%0], [%1], 16;" :: "r"(d), "l"(g));
}
#define CP_COMMIT  asm volatile("cp.async.commit_group;" ::: "memory")
#define CP_WAIT(n) asm volatile("cp.async.wait_group %0;" :: "n"(n) : "memory")

// ---------------- fused prep ----------------
#define PREP_X4   12582912
#define PREP_W1   (PREP_X4 + 131072)
#define PREP_W2   (PREP_W1 + 65536)
#define PREP_W3   (PREP_W2 + 65536)
#define PREP_IW   (PREP_W3 + 196608)
#define PREP_OW   (PREP_IW + 65536)
#define PREP_BLOCKS  (PREP_OW / 256)

__global__ void k_prep(const float* __restrict__ x,  const float* __restrict__ W1,
                       const float* __restrict__ W2, const float* __restrict__ W3,
                       const float* __restrict__ inW, const float* __restrict__ outW,
                       __half* __restrict__ x16)
{
    size_t gid = (size_t)blockIdx.x * blockDim.x + threadIdx.x;
    if (gid == 0) {
        const int ci[18] = {0,0,1,0,1,2,0,1,1,2,6,7,8,9,10,0,1,2};
        const int cj[18] = {1,2,2,3,3,3,4,4,5,5,7,8,9,10,11,6,9,11};
        float A[12][12];
        for (int i = 0; i < 12; i++)
            for (int j = 0; j < 12; j++) A[i][j] = (i == j) ? 1.0f : 0.0f;
        for (int e = 0; e < 18; e++) { A[ci[e]][cj[e]] = 1.0f; A[cj[e]][ci[e]] = 1.0f; }
        float dinv[12];
        for (int i = 0; i < 12; i++) {
            float s = 0.0f;
            for (int j = 0; j < 12; j++) s += A[i][j];
            dinv[i] = 1.0f / sqrtf(s);
        }
        for (int i = 0; i < 12; i++)
            for (int j = 0; j < 12; j++) g_A[i * 12 + j] = dinv[i] * A[i][j] * dinv[j];
    }
    if (gid < PREP_X4) {
        float4 v = ((const float4*)x)[gid];
        ((__half2*)x16)[gid * 2]     = __floats2half2_rn(v.x, v.y);
        ((__half2*)x16)[gid * 2 + 1] = __floats2half2_rn(v.z, v.w);
        return;
    }
    if (gid < PREP_W1) {
        size_t l = gid - PREP_X4;
        int k = (int)(l >> 8), n = (int)(l & 255);
        g_W1[n * FIN + k] = __float2half_rn(W1[l]);
        return;
    }
    if (gid < PREP_W2) {
        size_t l = gid - PREP_W1;
        int k = (int)(l >> 8), n = (int)(l & 255);
        g_W2[n * HID + k] = __float2half_rn(W2[l]);
        return;
    }
    if (gid < PREP_W3) {
        size_t l = gid - PREP_W2;
        int k = (int)(l >> 8), n = (int)(l & 255);
        g_W3[n * HID + k] = __float2half_rn(W3[l]);
        return;
    }
    if (gid < PREP_IW) {
        size_t l = gid - PREP_W3;
        g_Iw[l] = __float2half_rn(inW[l]);
        return;
    }
    if (gid < PREP_OW) {
        size_t l = gid - PREP_IW;
        g_Ow[l] = __float2half_rn(outW[l]);
        return;
    }
}

// ---------------- GEMM core ----------------
// Block tile 128x128, 128 threads (4 warps 2Mx2N), warp tile 64x64, BK=64.
// smem stage (half units, rows padded to SROW=72): A(128 rows)@0, B(128 rows)@9216.
// STAGE_H = 18432 half = 36864 B; 3 stages = 110592 B -> 2 CTAs/SM.
#define SROW    72
#define B_OFF_H (128 * SROW)
#define STAGE_H (256 * SROW)
#define STAGE_B (STAGE_H * 2)
#define NSTAGE  3
#define SMEM_BYTES (NSTAGE * STAGE_B)

struct GemmCtx {
    int lane, wm, wn;
    int arow, akblk, bn, bkblk, bntoff;
};

__device__ __forceinline__ GemmCtx make_ctx(int tid) {
    GemmCtx g;
    g.lane = tid & 31;
    int w = tid >> 5;         // 0..3
    g.wm = w >> 1;            // 0..1
    g.wn = w & 1;             // 0..1
    g.arow  = (g.lane & 7) | (((g.lane >> 3) & 1) << 3);
    g.akblk = (g.lane >> 4) & 1;
    int bwhich = g.lane >> 3;
    g.bn     = g.lane & 7;
    g.bkblk  = bwhich & 1;
    g.bntoff = bwhich >> 1;
    return g;
}

__device__ __forceinline__ void load_frags(const GemmCtx& g, uint32_t so, int ks,
                                           uint32_t ah[4][4], uint32_t bh[4][4]) {
#pragma unroll
    for (int mt = 0; mt < 4; mt++) {
        uint32_t aoff = so + ((g.wm * 64 + mt * 16 + g.arow) * SROW + ks * 16 + g.akblk * 8) * 2;
        ldsm4(ah[mt][0], ah[mt][1], ah[mt][2], ah[mt][3], aoff);
    }
#pragma unroll
    for (int p = 0; p < 4; p++) {
        int nt = p * 2 + g.bntoff;
        uint32_t boff = so + (B_OFF_H + (g.wn * 64 + nt * 8 + g.bn) * SROW + ks * 16 + g.bkblk * 8) * 2;
        ldsm4(bh[p][0], bh[p][1], bh[p][2], bh[p][3], boff);
    }
}

__device__ __forceinline__ void do_mmas(const uint32_t ah[4][4], const uint32_t bh[4][4],
                                        float c[4][8][4]) {
#pragma unroll
    for (int mt = 0; mt < 4; mt++)
#pragma unroll
        for (int p = 0; p < 4; p++)
#pragma unroll
            for (int h = 0; h < 2; h++)
                mma16816(c[mt][p * 2 + h], ah[mt], &bh[p][h * 2]);
}

template <bool BIAS>
__global__ __launch_bounds__(128, 2) void k_hgemm(
    const __half* __restrict__ A,
    const __half* __restrict__ B,
    const float* __restrict__ bias,
    __half* __restrict__ C,
    int K, int N)
{
    extern __shared__ __half sm[];
    const int tid  = threadIdx.x;
    const int row0 = blockIdx.y * 128;
    const int col0 = blockIdx.x * 128;
    const int NC   = K >> 6;                    // BK = 64
    const uint32_t sbase = smem_u32(sm);
    GemmCtx g = make_ctx(tid);

    float c[4][8][4];
#pragma unroll
    for (int i = 0; i < 4; i++)
#pragma unroll
        for (int j = 0; j < 8; j++)
#pragma unroll
            for (int q = 0; q < 4; q++) c[i][j][q] = 0.0f;

    const int rr = tid >> 3;                    // 0..15
    const int qq = (tid & 7) * 8;               // 0..56 halves
    const __half* Ab = A + (size_t)(row0 + rr) * K + qq;
    const __half* Bb = B + (size_t)(col0 + rr) * K + qq;
    const uint32_t doff = (rr * SROW + qq) * 2;

    auto cpa = [&](int cc) {
        uint32_t st = sbase + (cc % 3) * STAGE_B + doff;
        const __half* Ac = Ab + cc * 64;
        const __half* Bc = Bb + cc * 64;
#pragma unroll
        for (int u = 0; u < 8; u++)             // A: 8 x 16 rows
            cp16(st + u * 16 * SROW * 2, Ac + (size_t)(u * 16) * K);
#pragma unroll
        for (int u = 0; u < 8; u++)             // B: 8 x 16 rows
            cp16(st + (B_OFF_H + u * 16 * SROW) * 2, Bc + (size_t)(u * 16) * K);
    };

    int npre = NC < 2 ? NC : 2;
    for (int s = 0; s < npre; s++) { cpa(s); CP_COMMIT; }

    uint32_t ah[2][4][4], bh[2][4][4];

    for (int cc = 0; cc < NC; cc++) {
        if (cc + 1 < NC) CP_WAIT(1); else CP_WAIT(0);
        __syncthreads();
        if (cc + 2 < NC) { cpa(cc + 2); CP_COMMIT; }

        uint32_t so = sbase + (cc % 3) * STAGE_B;
        load_frags(g, so, 0, ah[0], bh[0]);
#pragma unroll
        for (int ks = 0; ks < 4; ks++) {
            int cur = ks & 1;
            if (ks < 3) load_frags(g, so, ks + 1, ah[cur ^ 1], bh[cur ^ 1]);
            do_mmas(ah[cur], bh[cur], c);
        }
        __syncthreads();
    }

    // epilogue
#pragma unroll
    for (int mt = 0; mt < 4; mt++) {
        int row = row0 + g.wm * 64 + mt * 16 + (g.lane >> 2);
#pragma unroll
        for (int n8 = 0; n8 < 8; n8++) {
            int col = col0 + g.wn * 64 + n8 * 8 + (g.lane & 3) * 2;
            float b0 = 0.0f, b1 = 0.0f;
            if (BIAS) { b0 = bias[col]; b1 = bias[col + 1]; }
            __half2 o0 = __floats2half2_rn(c[mt][n8][0] + b0, c[mt][n8][1] + b1);
            __half2 o1 = __floats2half2_rn(c[mt][n8][2] + b0, c[mt][n8][3] + b1);
            *(__half2*)(C + (size_t)row * N + col)       = o0;
            *(__half2*)(C + (size_t)(row + 8) * N + col) = o1;
        }
    }
}

// ---------------- lead-mix ----------------
template <bool RELU>
__global__ __launch_bounds__(256) void k_mix(
    const __half* __restrict__ T, const float* __restrict__ bias,
    __half* __restrict__ out)
{
    int b  = blockIdx.x * 2 + (threadIdx.x >> 7);
    int f2 = threadIdx.x & 127;
    const __half2* Tb = (const __half2*)(T + (size_t)b * LEADS * HID) + f2;
    float2 t[LEADS];
#pragma unroll
    for (int j = 0; j < LEADS; j++) t[j] = __half22float2(Tb[j * 128]);
    float b0 = bias[f2 * 2], b1 = bias[f2 * 2 + 1];
    __half2* Ob = (__half2*)(out + (size_t)b * LEADS * HID) + f2;
#pragma unroll
    for (int i = 0; i < LEADS; i++) {
        float ax = b0, ay = b1;
#pragma unroll
        for (int j = 0; j < LEADS; j++) {
            float w = g_A[i * 12 + j];
            ax += w * t[j].x; ay += w * t[j].y;
        }
        if (RELU) { ax = fmaxf(ax, 0.0f); ay = fmaxf(ay, 0.0f); }
        Ob[i * 128] = __floats2half2_rn(ax, ay);
    }
}

// ---------------- attention ----------------
__global__ __launch_bounds__(128) void k_attn(const __half* __restrict__ qkv,
                                              __half* __restrict__ o)
{
    __shared__ float sq[4][12 * 64];
    __shared__ float sk[4][12 * 64];
    __shared__ float sv[4][12 * 64];
    __shared__ float ss[4][12][12];

    int b    = blockIdx.x;
    int w    = threadIdx.x >> 5;
    int lane = threadIdx.x & 31;
    const __half* base = qkv + (size_t)b * LEADS * E3;

    for (int i2 = lane; i2 < 384; i2 += 32) {
        int s = i2 >> 5, d2 = (i2 & 31) * 2;
        float2 vq = __half22float2(*(const __half2*)(base + s * E3 +       w * 64 + d2));
        float2 vk = __half22float2(*(const __half2*)(base + s * E3 + 256 + w * 64 + d2));
        float2 vv = __half22float2(*(const __half2*)(base + s * E3 + 512 + w * 64 + d2));
        sq[w][s * 64 + d2] = vq.x; sq[w][s * 64 + d2 + 1] = vq.y;
        sk[w][s * 64 + d2] = vk.x; sk[w][s * 64 + d2 + 1] = vk.y;
        sv[w][s * 64 + d2] = vv.x; sv[w][s * 64 + d2 + 1] = vv.y;
    }
    __syncwarp();

    for (int st = lane; st < 144; st += 32) {
        int s = st / 12, t = st % 12;
        float acc = 0.0f;
#pragma unroll
        for (int d = 0; d < 64; d++) acc += sq[w][s * 64 + d] * sk[w][t * 64 + d];
        ss[w][s][t] = acc * 0.125f;
    }
    __syncwarp();

    if (lane < 12) {
        float mx = -1e30f;
        for (int t = 0; t < 12; t++) mx = fmaxf(mx, ss[w][lane][t]);
        float e[12], sum = 0.0f;
        for (int t = 0; t < 12; t++) { e[t] = expf(ss[w][lane][t] - mx); sum += e[t]; }
        float inv = 1.0f / sum;
        for (int t = 0; t < 12; t++) ss[w][lane][t] = e[t] * inv;
    }
    __syncwarp();

    for (int i2 = lane; i2 < 384; i2 += 32) {
        int s = i2 >> 5, d2 = (i2 & 31) * 2;
        float a0 = 0.0f, a1 = 0.0f;
#pragma unroll
        for (int t = 0; t < 12; t++) {
            float p = ss[w][s][t];
            a0 += p * sv[w][t * 64 + d2];
            a1 += p * sv[w][t * 64 + d2 + 1];
        }
        *(__half2*)(o + ((size_t)b * LEADS + s) * HID + w * 64 + d2) = __floats2half2_rn(a0, a1);
    }
}

// ---------------- residual + LayerNorm ----------------
__global__ __launch_bounds__(256) void k_ln(
    const __half* __restrict__ h, const __half* __restrict__ a,
    const float* __restrict__ g, const float* __restrict__ bta,
    __half* __restrict__ out)
{
    int row  = blockIdx.x * 8 + (threadIdx.x >> 5);
    int lane = threadIdx.x & 31;
    const __half2* hp = (const __half2*)(h + (size_t)row * HID);
    const __half2* ap = (const __half2*)(a + (size_t)row * HID);

    float v[8];
    float sum = 0.0f;
#pragma unroll
    for (int j = 0; j < 4; j++) {
        int c2 = lane + 32 * j;
        float2 hv = __half22float2(hp[c2]);
        float2 av = __half22float2(ap[c2]);
        v[2 * j]     = hv.x + av.x;
        v[2 * j + 1] = hv.y + av.y;
        sum += v[2 * j] + v[2 * j + 1];
    }
#pragma unroll
    for (int off = 16; off; off >>= 1) sum += __shfl_xor_sync(0xFFFFFFFFu, sum, off);
    float mu = sum * (1.0f / 256.0f);

    float vs = 0.0f;
#pragma unroll
    for (int j = 0; j < 8; j++) { float d = v[j] - mu; vs += d * d; }
#pragma unroll
    for (int off = 16; off; off >>= 1) vs += __shfl_xor_sync(0xFFFFFFFFu, vs, off);
    float rs = rsqrtf(vs * (1.0f / 256.0f) + 1e-5f);

    __half2* op = (__half2*)(out + (size_t)row * HID);
#pragma unroll
    for (int j = 0; j < 4; j++) {
        int c2 = lane + 32 * j;
        float o0 = (v[2 * j]     - mu) * rs * g[c2 * 2]     + bta[c2 * 2];
        float o1 = (v[2 * j + 1] - mu) * rs * g[c2 * 2 + 1] + bta[c2 * 2 + 1];
        op[c2] = __floats2half2_rn(o0, o1);
    }
}

// ---------------- final: gcn3 mix + pooling ----------------
__global__ __launch_bounds__(256) void k_final(
    const __half* __restrict__ T3, const float* __restrict__ b3,
    float* __restrict__ out)
{
    __shared__ float red[12][8];
    __shared__ float sw[12];
    int b = blockIdx.x, f = threadIdx.x;
    int lane = f & 31, wid = f >> 5;

    float t[LEADS];
#pragma unroll
    for (int j = 0; j < LEADS; j++)
        t[j] = __half2float(T3[((size_t)b * LEADS + j) * HID + f]);

    float bias = b3[f];
    float h3[LEADS];
#pragma unroll
    for (int i = 0; i < LEADS; i++) {
        float acc = bias;
#pragma unroll
        for (int j = 0; j < LEADS; j++) acc += g_A[i * 12 + j] * t[j];
        h3[i] = acc;
    }

#pragma unroll
    for (int i = 0; i < LEADS; i++) {
        float s = h3[i];
#pragma unroll
        for (int off = 16; off; off >>= 1) s += __shfl_xor_sync(0xFFFFFFFFu, s, off);
        if (lane == 0) red[i][wid] = s;
    }
    __syncthreads();
    if (f < 12) {
        float s = 0.0f;
        for (int w = 0; w < 8; w++) s += red[f][w];
        sw[f] = s * (1.0f / 256.0f);
    }
    __syncthreads();
    if (f == 0) {
        float mx = -1e30f;
        for (int i = 0; i < 12; i++) mx = fmaxf(mx, sw[i]);
        float e[12], sum = 0.0f;
        for (int i = 0; i < 12; i++) { e[i] = expf(sw[i] - mx); sum += e[i]; }
        float inv = 1.0f / sum;
        for (int i = 0; i < 12; i++) sw[i] = e[i] * inv;
    }
    __syncthreads();

    float ws = 0.0f, mx = -1e30f;
#pragma unroll
    for (int i = 0; i < LEADS; i++) {
        ws += h3[i] * sw[i];
        mx = fmaxf(mx, h3[i]);
    }
    out[(size_t)b * 512 + f]       = ws;
    out[(size_t)b * 512 + 256 + f] = mx;
}

// ---------------- launcher ----------------
extern "C" void kernel_launch(void* const* d_in, const int* in_sizes, int n_in,
                              void* d_out, int out_size)
{
    const float* x    = (const float*)d_in[0];
    const float* W1   = (const float*)d_in[1];
    const float* b1   = (const float*)d_in[2];
    const float* W2   = (const float*)d_in[3];
    const float* b2   = (const float*)d_in[4];
    const float* W3   = (const float*)d_in[5];
    const float* b3   = (const float*)d_in[6];
    const float* inW  = (const float*)d_in[7];
    const float* inB  = (const float*)d_in[8];
    const float* outW = (const float*)d_in[9];
    const float* outB = (const float*)d_in[10];
    const float* lng  = (const float*)d_in[11];
    const float* lnb  = (const float*)d_in[12];
    float* out = (float*)d_out;

    __half *bufQ, *buf1, *buf2, *buf3;
    cudaGetSymbolAddress((void**)&bufQ, g_qkv);
    cudaGetSymbolAddress((void**)&buf1, g_buf1);
    cudaGetSymbolAddress((void**)&buf2, g_buf2);
    cudaGetSymbolAddress((void**)&buf3, g_buf3);

    __half *w1, *w2, *w3, *iw, *ow;
    cudaGetSymbolAddress((void**)&w1, g_W1);
    cudaGetSymbolAddress((void**)&w2, g_W2);
    cudaGetSymbolAddress((void**)&w3, g_W3);
    cudaGetSymbolAddress((void**)&iw, g_Iw);
    cudaGetSymbolAddress((void**)&ow, g_Ow);

    cudaFuncSetAttribute(k_hgemm<false>, cudaFuncAttributeMaxDynamicSharedMemorySize, SMEM_BYTES);
    cudaFuncSetAttribute(k_hgemm<true>,  cudaFuncAttributeMaxDynamicSharedMemorySize, SMEM_BYTES);

    __half* x16 = bufQ;

    // 1: fused prep
    k_prep<<<PREP_BLOCKS, 256>>>(x, W1, W2, W3, inW, outW, x16);

    dim3 gH(2, MROWS / 128);   // N=256
    dim3 gQ(6, MROWS / 128);   // N=768

    // 2: gcn1 GEMM; 3: mix
    k_hgemm<false><<<gH, 128, SMEM_BYTES>>>(x16, w1, nullptr, buf1, FIN, HID);
    k_mix<true><<<B_SZ / 2, 256>>>(buf1, b1, buf2);

    // 4: gcn2 GEMM; 5: mix
    k_hgemm<false><<<gH, 128, SMEM_BYTES>>>(buf2, w2, nullptr, buf1, HID, HID);
    k_mix<true><<<B_SZ / 2, 256>>>(buf1, b2, buf3);     // buf3 = h2 (residual)

    // 6: qkv GEMM (ncu target)
    k_hgemm<true><<<gQ, 128, SMEM_BYTES>>>(buf3, iw, inB, bufQ, HID, E3);

    // 7: attention
    k_attn<<<B_SZ, 128>>>(bufQ, buf1);

    // 8: out_proj GEMM
    k_hgemm<true><<<gH, 128, SMEM_BYTES>>>(buf1, ow, outB, buf2, HID, HID);

    // 9: residual + LN
    k_ln<<<MROWS / 8, 256>>>(buf3, buf2, lng, lnb, buf1);

    // 10: gcn3 GEMM
    k_hgemm<false><<<gH, 128, SMEM_BYTES>>>(buf1, w3, nullptr, buf2, HID, HID);

    // 11: pooling
    k_final<<<B_SZ, 256>>>(buf2, b3, out);
}

// round 10
// speedup vs baseline: 1.0001x; 1.0001x over previous
#include <cuda_runtime.h>
#include <cuda_fp16.h>
#include <cstdint>
#include <math.h>

#define B_SZ   8192
#define LEADS  12
#define FIN    512
#define HID    256
#define E3     768
#define MROWS  (B_SZ * LEADS)   // 98304

// ---------------- static scratch ----------------
__device__ float g_A[LEADS * LEADS];
__device__ __half g_qkv[(size_t)MROWS * E3];   // also reused as x16 before qkv
__device__ __half g_buf1[(size_t)MROWS * HID];
__device__ __half g_buf2[(size_t)MROWS * HID];
__device__ __half g_buf3[(size_t)MROWS * HID];

__device__ __half g_W1[HID * FIN];
__device__ __half g_W2[HID * HID];
__device__ __half g_W3[HID * HID];
__device__ __half g_Iw[E3 * HID];
__device__ __half g_Ow[HID * HID];

// ---------------- helpers ----------------
__device__ __forceinline__ uint32_t smem_u32(const void* p) {
    uint32_t a;
    asm("{ .reg .u64 t; cvta.to.shared.u64 t, %1; cvt.u32.u64 %0, t; }" : "=r"(a) : "l"(p));
    return a;
}
__device__ __forceinline__ void ldsm4(uint32_t& r0, uint32_t& r1, uint32_t& r2, uint32_t& r3,
                                      uint32_t a) {
    asm volatile("ldmatrix.sync.aligned.m8n8.x4.shared.b16 {%0,%1,%2,%3}, [%4];"
                 : "=r"(r0), "=r"(r1), "=r"(r2), "=r"(r3) : "r"(a));
}
__device__ __forceinline__ void mma16816(float* c, const uint32_t* a, const uint32_t* b) {
    asm volatile("mma.sync.aligned.m16n8k16.row.col.f32.f16.f16.f32 "
                 "{%0,%1,%2,%3}, {%4,%5,%6,%7}, {%8,%9}, {%0,%1,%2,%3};"
                 : "+f"(c[0]), "+f"(c[1]), "+f"(c[2]), "+f"(c[3])
                 : "r"(a[0]), "r"(a[1]), "r"(a[2]), "r"(a[3]), "r"(b[0]), "r"(b[1]));
}
__device__ __forceinline__ void cp16(uint32_t d, const void* g) {
    asm volatile("cp.async.ca.shared.global [%0], [%1], 16;" :: "r"(d), "l"(g));
}
#define CP_COMMIT  asm volatile("cp.async.commit_group;" ::: "memory")
#define CP_WAIT(n) asm volatile("cp.async.wait_group %0;" :: "n"(n) : "memory")

// ---------------- fused prep ----------------
#define PREP_X4   12582912
#define PREP_W1   (PREP_X4 + 131072)
#define PREP_W2   (PREP_W1 + 65536)
#define PREP_W3   (PREP_W2 + 65536)
#define PREP_IW   (PREP_W3 + 196608)
#define PREP_OW   (PREP_IW + 65536)
#define PREP_BLOCKS  (PREP_OW / 256)

__global__ void k_prep(const float* __restrict__ x,  const float* __restrict__ W1,
                       const float* __restrict__ W2, const float* __restrict__ W3,
                       const float* __restrict__ inW, const float* __restrict__ outW,
                       __half* __restrict__ x16)
{
    size_t gid = (size_t)blockIdx.x * blockDim.x + threadIdx.x;
    if (gid == 0) {
        const int ci[18] = {0,0,1,0,1,2,0,1,1,2,6,7,8,9,10,0,1,2};
        const int cj[18] = {1,2,2,3,3,3,4,4,5,5,7,8,9,10,11,6,9,11};
        float A[12][12];
        for (int i = 0; i < 12; i++)
            for (int j = 0; j < 12; j++) A[i][j] = (i == j) ? 1.0f : 0.0f;
        for (int e = 0; e < 18; e++) { A[ci[e]][cj[e]] = 1.0f; A[cj[e]][ci[e]] = 1.0f; }
        float dinv[12];
        for (int i = 0; i < 12; i++) {
            float s = 0.0f;
            for (int j = 0; j < 12; j++) s += A[i][j];
            dinv[i] = 1.0f / sqrtf(s);
        }
        for (int i = 0; i < 12; i++)
            for (int j = 0; j < 12; j++) g_A[i * 12 + j] = dinv[i] * A[i][j] * dinv[j];
    }
    if (gid < PREP_X4) {
        float4 v = ((const float4*)x)[gid];
        ((__half2*)x16)[gid * 2]     = __floats2half2_rn(v.x, v.y);
        ((__half2*)x16)[gid * 2 + 1] = __floats2half2_rn(v.z, v.w);
        return;
    }
    if (gid < PREP_W1) {
        size_t l = gid - PREP_X4;
        int k = (int)(l >> 8), n = (int)(l & 255);
        g_W1[n * FIN + k] = __float2half_rn(W1[l]);
        return;
    }
    if (gid < PREP_W2) {
        size_t l = gid - PREP_W1;
        int k = (int)(l >> 8), n = (int)(l & 255);
        g_W2[n * HID + k] = __float2half_rn(W2[l]);
        return;
    }
    if (gid < PREP_W3) {
        size_t l = gid - PREP_W2;
        int k = (int)(l >> 8), n = (int)(l & 255);
        g_W3[n * HID + k] = __float2half_rn(W3[l]);
        return;
    }
    if (gid < PREP_IW) {
        size_t l = gid - PREP_W3;
        g_Iw[l] = __float2half_rn(inW[l]);
        return;
    }
    if (gid < PREP_OW) {
        size_t l = gid - PREP_IW;
        g_Ow[l] = __float2half_rn(outW[l]);
        return;
    }
}

// ---------------- GEMM core ----------------
// Block tile 128x256, 256 threads (8 warps 2Mx4N), warp tile 64x64, BK=64.
// smem stage (half units, rows padded to SROW=72): A(128 rows)@0, B(256 rows)@9216.
// STAGE_H = 27648 half = 55296 B; 3 stages = 165888 B.
// MODE: 0 = plain, 1 = +bias, 2 = +bias +residual +LayerNorm (fused epilogue).
#define SROW    72
#define B_OFF_H (128 * SROW)
#define STAGE_H (384 * SROW)
#define STAGE_B (STAGE_H * 2)
#define NSTAGE  3
#define SMEM_BYTES (NSTAGE * STAGE_B)
#define CST     260     // fp32 C-staging row stride (floats)

struct GemmCtx {
    int lane, wm, wn;
    int arow, akblk, bn, bkblk, bntoff;
};

__device__ __forceinline__ GemmCtx make_ctx(int tid) {
    GemmCtx g;
    g.lane = tid & 31;
    int w = tid >> 5;         // 0..7
    g.wm = w >> 2;            // 0..1 (M groups of 64)
    g.wn = w & 3;             // 0..3 (N groups of 64)
    g.arow  = (g.lane & 7) | (((g.lane >> 3) & 1) << 3);
    g.akblk = (g.lane >> 4) & 1;
    int bwhich = g.lane >> 3;
    g.bn     = g.lane & 7;
    g.bkblk  = bwhich & 1;
    g.bntoff = bwhich >> 1;
    return g;
}

__device__ __forceinline__ void load_frags(const GemmCtx& g, uint32_t so, int ks,
                                           uint32_t ah[4][4], uint32_t bh[4][4]) {
#pragma unroll
    for (int mt = 0; mt < 4; mt++) {
        uint32_t aoff = so + ((g.wm * 64 + mt * 16 + g.arow) * SROW + ks * 16 + g.akblk * 8) * 2;
        ldsm4(ah[mt][0], ah[mt][1], ah[mt][2], ah[mt][3], aoff);
    }
#pragma unroll
    for (int p = 0; p < 4; p++) {
        int nt = p * 2 + g.bntoff;
        uint32_t boff = so + (B_OFF_H + (g.wn * 64 + nt * 8 + g.bn) * SROW + ks * 16 + g.bkblk * 8) * 2;
        ldsm4(bh[p][0], bh[p][1], bh[p][2], bh[p][3], boff);
    }
}

__device__ __forceinline__ void do_mmas(const uint32_t ah[4][4], const uint32_t bh[4][4],
                                        float c[4][8][4]) {
#pragma unroll
    for (int mt = 0; mt < 4; mt++)
#pragma unroll
        for (int p = 0; p < 4; p++)
#pragma unroll
            for (int h = 0; h < 2; h++)
                mma16816(c[mt][p * 2 + h], ah[mt], &bh[p][h * 2]);
}

template <int MODE>
__global__ __launch_bounds__(256, 1) void k_hgemm(
    const __half* __restrict__ A,
    const __half* __restrict__ B,
    const float* __restrict__ bias,
    __half* __restrict__ C,
    int K, int N,
    const __half* __restrict__ resid,
    const float* __restrict__ lng,
    const float* __restrict__ lnb)
{
    extern __shared__ __half sm[];
    const int tid  = threadIdx.x;
    const int row0 = blockIdx.y * 128;
    const int col0 = blockIdx.x * 256;
    const int NC   = K >> 6;                    // BK = 64
    const uint32_t sbase = smem_u32(sm);
    GemmCtx g = make_ctx(tid);

    float c[4][8][4];
#pragma unroll
    for (int i = 0; i < 4; i++)
#pragma unroll
        for (int j = 0; j < 8; j++)
#pragma unroll
            for (int q = 0; q < 4; q++) c[i][j][q] = 0.0f;

    const int rr = tid >> 3;                    // 0..31
    const int qq = (tid & 7) * 8;               // 0..56 halves
    const __half* Ab = A + (size_t)(row0 + rr) * K + qq;
    const __half* Bb = B + (size_t)(col0 + rr) * K + qq;
    const uint32_t doff = (rr * SROW + qq) * 2;

    auto cpa = [&](int cc) {
        uint32_t st = sbase + (cc % 3) * STAGE_B + doff;
        const __half* Ac = Ab + cc * 64;
        const __half* Bc = Bb + cc * 64;
#pragma unroll
        for (int u = 0; u < 4; u++)             // A: 4 x 32 rows
            cp16(st + u * 32 * SROW * 2, Ac + (size_t)(u * 32) * K);
#pragma unroll
        for (int u = 0; u < 8; u++)             // B: 8 x 32 rows
            cp16(st + (B_OFF_H + u * 32 * SROW) * 2, Bc + (size_t)(u * 32) * K);
    };

    int npre = NC < 2 ? NC : 2;
    for (int s = 0; s < npre; s++) { cpa(s); CP_COMMIT; }

    uint32_t ah[2][4][4], bh[2][4][4];

    for (int cc = 0; cc < NC; cc++) {
        if (cc + 1 < NC) CP_WAIT(1); else CP_WAIT(0);
        __syncthreads();
        if (cc + 2 < NC) { cpa(cc + 2); CP_COMMIT; }

        uint32_t so = sbase + (cc % 3) * STAGE_B;
        load_frags(g, so, 0, ah[0], bh[0]);
#pragma unroll
        for (int ks = 0; ks < 4; ks++) {
            int cur = ks & 1;
            if (ks < 3) load_frags(g, so, ks + 1, ah[cur ^ 1], bh[cur ^ 1]);
            do_mmas(ah[cur], bh[cur], c);
        }
        __syncthreads();
    }

    if (MODE < 2) {
        // direct epilogue
#pragma unroll
        for (int mt = 0; mt < 4; mt++) {
            int row = row0 + g.wm * 64 + mt * 16 + (g.lane >> 2);
#pragma unroll
            for (int n8 = 0; n8 < 8; n8++) {
                int col = col0 + g.wn * 64 + n8 * 8 + (g.lane & 3) * 2;
                float b0 = 0.0f, b1 = 0.0f;
                if (MODE == 1) { b0 = bias[col]; b1 = bias[col + 1]; }
                __half2 o0 = __floats2half2_rn(c[mt][n8][0] + b0, c[mt][n8][1] + b1);
                __half2 o1 = __floats2half2_rn(c[mt][n8][2] + b0, c[mt][n8][3] + b1);
                *(__half2*)(C + (size_t)row * N + col)       = o0;
                *(__half2*)(C + (size_t)(row + 8) * N + col) = o1;
            }
        }
    } else {
        // fused bias + residual + LayerNorm epilogue (N must be 256, grid.x == 1)
        float* Cst = (float*)sm;
        __syncthreads();     // done with stage buffers
#pragma unroll
        for (int mt = 0; mt < 4; mt++) {
            int r = g.wm * 64 + mt * 16 + (g.lane >> 2);
#pragma unroll
            for (int n8 = 0; n8 < 8; n8++) {
                int col = g.wn * 64 + n8 * 8 + (g.lane & 3) * 2;
                float b0 = bias[col], b1 = bias[col + 1];
                Cst[r * CST + col]           = c[mt][n8][0] + b0;
                Cst[r * CST + col + 1]       = c[mt][n8][1] + b1;
                Cst[(r + 8) * CST + col]     = c[mt][n8][2] + b0;
                Cst[(r + 8) * CST + col + 1] = c[mt][n8][3] + b1;
            }
        }
        __syncthreads();

        const int w    = tid >> 5;
        const int lane = g.lane;
        // per-lane gamma/beta (8 cols each)
        float gv[8], bv[8];
#pragma unroll
        for (int j = 0; j < 8; j++) {
            gv[j] = lng[lane * 8 + j];
            bv[j] = lnb[lane * 8 + j];
        }
        for (int r2 = 0; r2 < 16; r2++) {
            int r = w * 16 + r2;
            size_t grow = (size_t)(row0 + r);
            // residual (8 halves)
            uint4 hraw = *(const uint4*)(resid + grow * 256 + lane * 8);
            __half2* hx = (__half2*)&hraw;
            float v[8];
            float sum = 0.0f;
#pragma unroll
            for (int j = 0; j < 4; j++) {
                float2 f = __half22float2(hx[j]);
                v[2 * j]     = Cst[r * CST + lane * 8 + 2 * j]     + f.x;
                v[2 * j + 1] = Cst[r * CST + lane * 8 + 2 * j + 1] + f.y;
                sum += v[2 * j] + v[2 * j + 1];
            }
#pragma unroll
            for (int off = 16; off; off >>= 1) sum += __shfl_xor_sync(0xFFFFFFFFu, sum, off);
            float mu = sum * (1.0f / 256.0f);
            float vs = 0.0f;
#pragma unroll
            for (int j = 0; j < 8; j++) { float d = v[j] - mu; vs += d * d; }
#pragma unroll
            for (int off = 16; off; off >>= 1) vs += __shfl_xor_sync(0xFFFFFFFFu, vs, off);
            float rs = rsqrtf(vs * (1.0f / 256.0f) + 1e-5f);

            uint4 oraw;
            __half2* ox = (__half2*)&oraw;
#pragma unroll
            for (int j = 0; j < 4; j++) {
                float o0 = (v[2 * j]     - mu) * rs * gv[2 * j]     + bv[2 * j];
                float o1 = (v[2 * j + 1] - mu) * rs * gv[2 * j + 1] + bv[2 * j + 1];
                ox[j] = __floats2half2_rn(o0, o1);
            }
            *(uint4*)(C + grow * 256 + lane * 8) = oraw;
        }
    }
}

// ---------------- lead-mix ----------------
template <bool RELU>
__global__ __launch_bounds__(256) void k_mix(
    const __half* __restrict__ T, const float* __restrict__ bias,
    __half* __restrict__ out)
{
    int b  = blockIdx.x * 2 + (threadIdx.x >> 7);
    int f2 = threadIdx.x & 127;
    const __half2* Tb = (const __half2*)(T + (size_t)b * LEADS * HID) + f2;
    float2 t[LEADS];
#pragma unroll
    for (int j = 0; j < LEADS; j++) t[j] = __half22float2(Tb[j * 128]);
    float b0 = bias[f2 * 2], b1 = bias[f2 * 2 + 1];
    __half2* Ob = (__half2*)(out + (size_t)b * LEADS * HID) + f2;
#pragma unroll
    for (int i = 0; i < LEADS; i++) {
        float ax = b0, ay = b1;
#pragma unroll
        for (int j = 0; j < LEADS; j++) {
            float w = g_A[i * 12 + j];
            ax += w * t[j].x; ay += w * t[j].y;
        }
        if (RELU) { ax = fmaxf(ax, 0.0f); ay = fmaxf(ay, 0.0f); }
        Ob[i * 128] = __floats2half2_rn(ax, ay);
    }
}

// ---------------- attention ----------------
__global__ __launch_bounds__(128) void k_attn(const __half* __restrict__ qkv,
                                              __half* __restrict__ o)
{
    __shared__ float sq[4][12 * 64];
    __shared__ float sk[4][12 * 64];
    __shared__ float sv[4][12 * 64];
    __shared__ float ss[4][12][12];

    int b    = blockIdx.x;
    int w    = threadIdx.x >> 5;
    int lane = threadIdx.x & 31;
    const __half* base = qkv + (size_t)b * LEADS * E3;

    for (int i2 = lane; i2 < 384; i2 += 32) {
        int s = i2 >> 5, d2 = (i2 & 31) * 2;
        float2 vq = __half22float2(*(const __half2*)(base + s * E3 +       w * 64 + d2));
        float2 vk = __half22float2(*(const __half2*)(base + s * E3 + 256 + w * 64 + d2));
        float2 vv = __half22float2(*(const __half2*)(base + s * E3 + 512 + w * 64 + d2));
        sq[w][s * 64 + d2] = vq.x; sq[w][s * 64 + d2 + 1] = vq.y;
        sk[w][s * 64 + d2] = vk.x; sk[w][s * 64 + d2 + 1] = vk.y;
        sv[w][s * 64 + d2] = vv.x; sv[w][s * 64 + d2 + 1] = vv.y;
    }
    __syncwarp();

    for (int st = lane; st < 144; st += 32) {
        int s = st / 12, t = st % 12;
        float acc = 0.0f;
#pragma unroll
        for (int d = 0; d < 64; d++) acc += sq[w][s * 64 + d] * sk[w][t * 64 + d];
        ss[w][s][t] = acc * 0.125f;
    }
    __syncwarp();

    if (lane < 12) {
        float mx = -1e30f;
        for (int t = 0; t < 12; t++) mx = fmaxf(mx, ss[w][lane][t]);
        float e[12], sum = 0.0f;
        for (int t = 0; t < 12; t++) { e[t] = expf(ss[w][lane][t] - mx); sum += e[t]; }
        float inv = 1.0f / sum;
        for (int t = 0; t < 12; t++) ss[w][lane][t] = e[t] * inv;
    }
    __syncwarp();

    for (int i2 = lane; i2 < 384; i2 += 32) {
        int s = i2 >> 5, d2 = (i2 & 31) * 2;
        float a0 = 0.0f, a1 = 0.0f;
#pragma unroll
        for (int t = 0; t < 12; t++) {
            float p = ss[w][s][t];
            a0 += p * sv[w][t * 64 + d2];
            a1 += p * sv[w][t * 64 + d2 + 1];
        }
        *(__half2*)(o + ((size_t)b * LEADS + s) * HID + w * 64 + d2) = __floats2half2_rn(a0, a1);
    }
}

// ---------------- final: gcn3 mix + pooling ----------------
__global__ __launch_bounds__(256) void k_final(
    const __half* __restrict__ T3, const float* __restrict__ b3,
    float* __restrict__ out)
{
    __shared__ float red[12][8];
    __shared__ float sw[12];
    int b = blockIdx.x, f = threadIdx.x;
    int lane = f & 31, wid = f >> 5;

    float t[LEADS];
#pragma unroll
    for (int j = 0; j < LEADS; j++)
        t[j] = __half2float(T3[((size_t)b * LEADS + j) * HID + f]);

    float bias = b3[f];
    float h3[LEADS];
#pragma unroll
    for (int i = 0; i < LEADS; i++) {
        float acc = bias;
#pragma unroll
        for (int j = 0; j < LEADS; j++) acc += g_A[i * 12 + j] * t[j];
        h3[i] = acc;
    }

#pragma unroll
    for (int i = 0; i < LEADS; i++) {
        float s = h3[i];
#pragma unroll
        for (int off = 16; off; off >>= 1) s += __shfl_xor_sync(0xFFFFFFFFu, s, off);
        if (lane == 0) red[i][wid] = s;
    }
    __syncthreads();
    if (f < 12) {
        float s = 0.0f;
        for (int w = 0; w < 8; w++) s += red[f][w];
        sw[f] = s * (1.0f / 256.0f);
    }
    __syncthreads();
    if (f == 0) {
        float mx = -1e30f;
        for (int i = 0; i < 12; i++) mx = fmaxf(mx, sw[i]);
        float e[12], sum = 0.0f;
        for (int i = 0; i < 12; i++) { e[i] = expf(sw[i] - mx); sum += e[i]; }
        float inv = 1.0f / sum;
        for (int i = 0; i < 12; i++) sw[i] = e[i] * inv;
    }
    __syncthreads();

    float ws = 0.0f, mx = -1e30f;
#pragma unroll
    for (int i = 0; i < LEADS; i++) {
        ws += h3[i] * sw[i];
        mx = fmaxf(mx, h3[i]);
    }
    out[(size_t)b * 512 + f]       = ws;
    out[(size_t)b * 512 + 256 + f] = mx;
}

// ---------------- launcher ----------------
extern "C" void kernel_launch(void* const* d_in, const int* in_sizes, int n_in,
                              void* d_out, int out_size)
{
    const float* x    = (const float*)d_in[0];
    const float* W1   = (const float*)d_in[1];
    const float* b1   = (const float*)d_in[2];
    const float* W2   = (const float*)d_in[3];
    const float* b2   = (const float*)d_in[4];
    const float* W3   = (const float*)d_in[5];
    const float* b3   = (const float*)d_in[6];
    const float* inW  = (const float*)d_in[7];
    const float* inB  = (const float*)d_in[8];
    const float* outW = (const float*)d_in[9];
    const float* outB = (const float*)d_in[10];
    const float* lng  = (const float*)d_in[11];
    const float* lnb  = (const float*)d_in[12];
    float* out = (float*)d_out;

    __half *bufQ, *buf1, *buf2, *buf3;
    cudaGetSymbolAddress((void**)&bufQ, g_qkv);
    cudaGetSymbolAddress((void**)&buf1, g_buf1);
    cudaGetSymbolAddress((void**)&buf2, g_buf2);
    cudaGetSymbolAddress((void**)&buf3, g_buf3);

    __half *w1, *w2, *w3, *iw, *ow;
    cudaGetSymbolAddress((void**)&w1, g_W1);
    cudaGetSymbolAddress((void**)&w2, g_W2);
    cudaGetSymbolAddress((void**)&w3, g_W3);
    cudaGetSymbolAddress((void**)&iw, g_Iw);
    cudaGetSymbolAddress((void**)&ow, g_Ow);

    cudaFuncSetAttribute(k_hgemm<0>, cudaFuncAttributeMaxDynamicSharedMemorySize, SMEM_BYTES);
    cudaFuncSetAttribute(k_hgemm<1>, cudaFuncAttributeMaxDynamicSharedMemorySize, SMEM_BYTES);
    cudaFuncSetAttribute(k_hgemm<2>, cudaFuncAttributeMaxDynamicSharedMemorySize, SMEM_BYTES);

    __half* x16 = bufQ;

    // 1: fused prep
    k_prep<<<PREP_BLOCKS, 256>>>(x, W1, W2, W3, inW, outW, x16);

    dim3 gH(1, MROWS / 128);   // N=256: one N-tile -> A read once
    dim3 gQ(3, MROWS / 128);   // N=768

    // 2: gcn1 GEMM; 3: mix
    k_hgemm<0><<<gH, 256, SMEM_BYTES>>>(x16, w1, nullptr, buf1, FIN, HID, nullptr, nullptr, nullptr);
    k_mix<true><<<B_SZ / 2, 256>>>(buf1, b1, buf2);

    // 4: gcn2 GEMM; 5: mix
    k_hgemm<0><<<gH, 256, SMEM_BYTES>>>(buf2, w2, nullptr, buf1, HID, HID, nullptr, nullptr, nullptr);
    k_mix<true><<<B_SZ / 2, 256>>>(buf1, b2, buf3);     // buf3 = h2 (residual)

    // 6: qkv GEMM
    k_hgemm<1><<<gQ, 256, SMEM_BYTES>>>(buf3, iw, inB, bufQ, HID, E3, nullptr, nullptr, nullptr);

    // 7: attention -> buf1
    k_attn<<<B_SZ, 128>>>(bufQ, buf1);

    // 8: out_proj GEMM + bias + residual(h2=buf3) + LayerNorm, in-place -> buf1
    k_hgemm<2><<<gH, 256, SMEM_BYTES>>>(buf1, ow, outB, buf1, HID, HID, buf3, lng, lnb);

    // 9: gcn3 GEMM
    k_hgemm<0><<<gH, 256, SMEM_BYTES>>>(buf1, w3, nullptr, buf2, HID, HID, nullptr, nullptr, nullptr);

    // 10: pooling
    k_final<<<B_SZ, 256>>>(buf2, b3, out);
}

// round 11
// speedup vs baseline: 1.3284x; 1.3283x over previous
#include <cuda_runtime.h>
#include <cuda_fp16.h>
#include <cstdint>
#include <math.h>

#define B_SZ   8192
#define LEADS  12
#define FIN    512
#define HID    256
#define E3     768
#define MROWS  (B_SZ * LEADS)   // 98304

// ---------------- static scratch ----------------
__device__ float g_A[LEADS * LEADS];
__device__ __half g_qkv[(size_t)MROWS * E3];   // also reused as x16 before qkv
__device__ __half g_buf1[(size_t)MROWS * HID];
__device__ __half g_buf2[(size_t)MROWS * HID];
__device__ __half g_buf3[(size_t)MROWS * HID];

__device__ __half g_W1[HID * FIN];
__device__ __half g_W2[HID * HID];
__device__ __half g_W3[HID * HID];
__device__ __half g_Iw[E3 * HID];
__device__ __half g_Ow[HID * HID];

// ---------------- helpers ----------------
__device__ __forceinline__ uint32_t smem_u32(const void* p) {
    uint32_t a;
    asm("{ .reg .u64 t; cvta.to.shared.u64 t, %1; cvt.u32.u64 %0, t; }" : "=r"(a) : "l"(p));
    return a;
}
__device__ __forceinline__ void ldsm4(uint32_t& r0, uint32_t& r1, uint32_t& r2, uint32_t& r3,
                                      uint32_t a) {
    asm volatile("ldmatrix.sync.aligned.m8n8.x4.shared.b16 {%0,%1,%2,%3}, [%4];"
                 : "=r"(r0), "=r"(r1), "=r"(r2), "=r"(r3) : "r"(a));
}
__device__ __forceinline__ void mma16816(float* c, const uint32_t* a, const uint32_t* b) {
    asm volatile("mma.sync.aligned.m16n8k16.row.col.f32.f16.f16.f32 "
                 "{%0,%1,%2,%3}, {%4,%5,%6,%7}, {%8,%9}, {%0,%1,%2,%3};"
                 : "+f"(c[0]), "+f"(c[1]), "+f"(c[2]), "+f"(c[3])
                 : "r"(a[0]), "r"(a[1]), "r"(a[2]), "r"(a[3]), "r"(b[0]), "r"(b[1]));
}
__device__ __forceinline__ void cp16(uint32_t d, const void* g) {
    asm volatile("cp.async.ca.shared.global [%0], [%1], 16;" :: "r"(d), "l"(g));
}
#define CP_COMMIT  asm volatile("cp.async.commit_group;" ::: "memory")
#define CP_WAIT(n) asm volatile("cp.async.wait_group %0;" :: "n"(n) : "memory")

// ---------------- fused prep ----------------
#define PREP_X4   12582912
#define PREP_W1   (PREP_X4 + 131072)
#define PREP_W2   (PREP_W1 + 65536)
#define PREP_W3   (PREP_W2 + 65536)
#define PREP_IW   (PREP_W3 + 196608)
#define PREP_OW   (PREP_IW + 65536)
#define PREP_BLOCKS  (PREP_OW / 256)

__global__ void k_prep(const float* __restrict__ x,  const float* __restrict__ W1,
                       const float* __restrict__ W2, const float* __restrict__ W3,
                       const float* __restrict__ inW, const float* __restrict__ outW,
                       __half* __restrict__ x16)
{
    size_t gid = (size_t)blockIdx.x * blockDim.x + threadIdx.x;
    if (gid == 0) {
        const int ci[18] = {0,0,1,0,1,2,0,1,1,2,6,7,8,9,10,0,1,2};
        const int cj[18] = {1,2,2,3,3,3,4,4,5,5,7,8,9,10,11,6,9,11};
        float A[12][12];
        for (int i = 0; i < 12; i++)
            for (int j = 0; j < 12; j++) A[i][j] = (i == j) ? 1.0f : 0.0f;
        for (int e = 0; e < 18; e++) { A[ci[e]][cj[e]] = 1.0f; A[cj[e]][ci[e]] = 1.0f; }
        float dinv[12];
        for (int i = 0; i < 12; i++) {
            float s = 0.0f;
            for (int j = 0; j < 12; j++) s += A[i][j];
            dinv[i] = 1.0f / sqrtf(s);
        }
        for (int i = 0; i < 12; i++)
            for (int j = 0; j < 12; j++) g_A[i * 12 + j] = dinv[i] * A[i][j] * dinv[j];
    }
    if (gid < PREP_X4) {
        float4 v = ((const float4*)x)[gid];
        ((__half2*)x16)[gid * 2]     = __floats2half2_rn(v.x, v.y);
        ((__half2*)x16)[gid * 2 + 1] = __floats2half2_rn(v.z, v.w);
        return;
    }
    if (gid < PREP_W1) {
        size_t l = gid - PREP_X4;
        int k = (int)(l >> 8), n = (int)(l & 255);
        g_W1[n * FIN + k] = __float2half_rn(W1[l]);
        return;
    }
    if (gid < PREP_W2) {
        size_t l = gid - PREP_W1;
        int k = (int)(l >> 8), n = (int)(l & 255);
        g_W2[n * HID + k] = __float2half_rn(W2[l]);
        return;
    }
    if (gid < PREP_W3) {
        size_t l = gid - PREP_W2;
        int k = (int)(l >> 8), n = (int)(l & 255);
        g_W3[n * HID + k] = __float2half_rn(W3[l]);
        return;
    }
    if (gid < PREP_IW) {
        size_t l = gid - PREP_W3;
        g_Iw[l] = __float2half_rn(inW[l]);
        return;
    }
    if (gid < PREP_OW) {
        size_t l = gid - PREP_IW;
        g_Ow[l] = __float2half_rn(outW[l]);
        return;
    }
}

// ---------------- GEMM core (R8 geometry, unchanged) ----------------
// Block tile 256x128, 256 threads (8 warps 4Mx2N), warp tile 64x64, BK=64.
#define SROW    72
#define B_OFF_H (256 * SROW)
#define STAGE_H (384 * SROW)
#define STAGE_B (STAGE_H * 2)
#define NSTAGE  3
#define SMEM_BYTES (NSTAGE * STAGE_B)

struct GemmCtx {
    int lane, wm, wn;
    int arow, akblk, bn, bkblk, bntoff;
};

__device__ __forceinline__ GemmCtx make_ctx(int tid) {
    GemmCtx g;
    g.lane = tid & 31;
    int w = tid >> 5;
    g.wm = w >> 1;
    g.wn = w & 1;
    g.arow  = (g.lane & 7) | (((g.lane >> 3) & 1) << 3);
    g.akblk = (g.lane >> 4) & 1;
    int bwhich = g.lane >> 3;
    g.bn     = g.lane & 7;
    g.bkblk  = bwhich & 1;
    g.bntoff = bwhich >> 1;
    return g;
}

__device__ __forceinline__ void load_frags(const GemmCtx& g, uint32_t so, int ks,
                                           uint32_t ah[4][4], uint32_t bh[4][4]) {
#pragma unroll
    for (int mt = 0; mt < 4; mt++) {
        uint32_t aoff = so + ((g.wm * 64 + mt * 16 + g.arow) * SROW + ks * 16 + g.akblk * 8) * 2;
        ldsm4(ah[mt][0], ah[mt][1], ah[mt][2], ah[mt][3], aoff);
    }
#pragma unroll
    for (int p = 0; p < 4; p++) {
        int nt = p * 2 + g.bntoff;
        uint32_t boff = so + (B_OFF_H + (g.wn * 64 + nt * 8 + g.bn) * SROW + ks * 16 + g.bkblk * 8) * 2;
        ldsm4(bh[p][0], bh[p][1], bh[p][2], bh[p][3], boff);
    }
}

__device__ __forceinline__ void do_mmas(const uint32_t ah[4][4], const uint32_t bh[4][4],
                                        float c[4][8][4]) {
#pragma unroll
    for (int mt = 0; mt < 4; mt++)
#pragma unroll
        for (int p = 0; p < 4; p++)
#pragma unroll
            for (int h = 0; h < 2; h++)
                mma16816(c[mt][p * 2 + h], ah[mt], &bh[p][h * 2]);
}

template <bool BIAS>
__global__ __launch_bounds__(256, 1) void k_hgemm(
    const __half* __restrict__ A,
    const __half* __restrict__ B,
    const float* __restrict__ bias,
    __half* __restrict__ C,
    int K, int N)
{
    extern __shared__ __half sm[];
    const int tid  = threadIdx.x;
    const int row0 = blockIdx.y * 256;
    const int col0 = blockIdx.x * 128;
    const int NC   = K >> 6;                    // BK = 64
    const uint32_t sbase = smem_u32(sm);
    GemmCtx g = make_ctx(tid);

    float c[4][8][4];
#pragma unroll
    for (int i = 0; i < 4; i++)
#pragma unroll
        for (int j = 0; j < 8; j++)
#pragma unroll
            for (int q = 0; q < 4; q++) c[i][j][q] = 0.0f;

    const int rr = tid >> 3;                    // 0..31
    const int qq = (tid & 7) * 8;               // 0..56 halves
    const __half* Ab = A + (size_t)(row0 + rr) * K + qq;
    const __half* Bb = B + (size_t)(col0 + rr) * K + qq;
    const uint32_t doff = (rr * SROW + qq) * 2;

    auto cpa = [&](int cc) {
        uint32_t st = sbase + (cc % 3) * STAGE_B + doff;
        const __half* Ac = Ab + cc * 64;
        const __half* Bc = Bb + cc * 64;
#pragma unroll
        for (int u = 0; u < 8; u++)             // A: 8 x 32 rows
            cp16(st + u * 32 * SROW * 2, Ac + (size_t)(u * 32) * K);
#pragma unroll
        for (int u = 0; u < 4; u++)             // B: 4 x 32 rows
            cp16(st + (B_OFF_H + u * 32 * SROW) * 2, Bc + (size_t)(u * 32) * K);
    };

    int npre = NC < 2 ? NC : 2;
    for (int s = 0; s < npre; s++) { cpa(s); CP_COMMIT; }

    uint32_t ah[2][4][4], bh[2][4][4];

    for (int cc = 0; cc < NC; cc++) {
        if (cc + 1 < NC) CP_WAIT(1); else CP_WAIT(0);
        __syncthreads();
        if (cc + 2 < NC) { cpa(cc + 2); CP_COMMIT; }

        uint32_t so = sbase + (cc % 3) * STAGE_B;
        load_frags(g, so, 0, ah[0], bh[0]);
#pragma unroll
        for (int ks = 0; ks < 4; ks++) {
            int cur = ks & 1;
            if (ks < 3) load_frags(g, so, ks + 1, ah[cur ^ 1], bh[cur ^ 1]);
            do_mmas(ah[cur], bh[cur], c);
        }
        __syncthreads();
    }

    // epilogue
#pragma unroll
    for (int mt = 0; mt < 4; mt++) {
        int row = row0 + g.wm * 64 + mt * 16 + (g.lane >> 2);
#pragma unroll
        for (int n8 = 0; n8 < 8; n8++) {
            int col = col0 + g.wn * 64 + n8 * 8 + (g.lane & 3) * 2;
            float b0 = 0.0f, b1 = 0.0f;
            if (BIAS) { b0 = bias[col]; b1 = bias[col + 1]; }
            __half2 o0 = __floats2half2_rn(c[mt][n8][0] + b0, c[mt][n8][1] + b1);
            __half2 o1 = __floats2half2_rn(c[mt][n8][2] + b0, c[mt][n8][3] + b1);
            *(__half2*)(C + (size_t)row * N + col)       = o0;
            *(__half2*)(C + (size_t)(row + 8) * N + col) = o1;
        }
    }
}

// ---------------- lead-mix ----------------
template <bool RELU>
__global__ __launch_bounds__(256) void k_mix(
    const __half* __restrict__ T, const float* __restrict__ bias,
    __half* __restrict__ out)
{
    int b  = blockIdx.x * 2 + (threadIdx.x >> 7);
    int f2 = threadIdx.x & 127;
    const __half2* Tb = (const __half2*)(T + (size_t)b * LEADS * HID) + f2;
    float2 t[LEADS];
#pragma unroll
    for (int j = 0; j < LEADS; j++) t[j] = __half22float2(Tb[j * 128]);
    float b0 = bias[f2 * 2], b1 = bias[f2 * 2 + 1];
    __half2* Ob = (__half2*)(out + (size_t)b * LEADS * HID) + f2;
#pragma unroll
    for (int i = 0; i < LEADS; i++) {
        float ax = b0, ay = b1;
#pragma unroll
        for (int j = 0; j < LEADS; j++) {
            float w = g_A[i * 12 + j];
            ax += w * t[j].x; ay += w * t[j].y;
        }
        if (RELU) { ax = fmaxf(ax, 0.0f); ay = fmaxf(ay, 0.0f); }
        Ob[i * 128] = __floats2half2_rn(ax, ay);
    }
}

// ---------------- attention (bank-conflict-free: row stride 65) ----------------
#define QS 65
__global__ __launch_bounds__(128) void k_attn(const __half* __restrict__ qkv,
                                              __half* __restrict__ o)
{
    __shared__ float sq[4][12 * QS];
    __shared__ float sk[4][12 * QS];
    __shared__ float sv[4][12 * QS];
    __shared__ float ss[4][12][12];

    int b    = blockIdx.x;
    int w    = threadIdx.x >> 5;
    int lane = threadIdx.x & 31;
    const __half* base = qkv + (size_t)b * LEADS * E3;

    for (int i2 = lane; i2 < 384; i2 += 32) {
        int s = i2 >> 5, d2 = (i2 & 31) * 2;
        float2 vq = __half22float2(*(const __half2*)(base + s * E3 +       w * 64 + d2));
        float2 vk = __half22float2(*(const __half2*)(base + s * E3 + 256 + w * 64 + d2));
        float2 vv = __half22float2(*(const __half2*)(base + s * E3 + 512 + w * 64 + d2));
        sq[w][s * QS + d2] = vq.x; sq[w][s * QS + d2 + 1] = vq.y;
        sk[w][s * QS + d2] = vk.x; sk[w][s * QS + d2 + 1] = vk.y;
        sv[w][s * QS + d2] = vv.x; sv[w][s * QS + d2 + 1] = vv.y;
    }
    __syncwarp();

    for (int st = lane; st < 144; st += 32) {
        int s = st / 12, t = st % 12;
        float acc = 0.0f;
#pragma unroll
        for (int d = 0; d < 64; d++) acc += sq[w][s * QS + d] * sk[w][t * QS + d];
        ss[w][s][t] = acc * 0.125f;
    }
    __syncwarp();

    if (lane < 12) {
        float mx = -1e30f;
        for (int t = 0; t < 12; t++) mx = fmaxf(mx, ss[w][lane][t]);
        float e[12], sum = 0.0f;
        for (int t = 0; t < 12; t++) { e[t] = expf(ss[w][lane][t] - mx); sum += e[t]; }
        float inv = 1.0f / sum;
        for (int t = 0; t < 12; t++) ss[w][lane][t] = e[t] * inv;
    }
    __syncwarp();

    for (int i2 = lane; i2 < 384; i2 += 32) {
        int s = i2 >> 5, d2 = (i2 & 31) * 2;
        float a0 = 0.0f, a1 = 0.0f;
#pragma unroll
        for (int t = 0; t < 12; t++) {
            float p = ss[w][s][t];
            a0 += p * sv[w][t * QS + d2];
            a1 += p * sv[w][t * QS + d2 + 1];
        }
        *(__half2*)(o + ((size_t)b * LEADS + s) * HID + w * 64 + d2) = __floats2half2_rn(a0, a1);
    }
}

// ---------------- residual + LayerNorm ----------------
__global__ __launch_bounds__(256) void k_ln(
    const __half* __restrict__ h, const __half* __restrict__ a,
    const float* __restrict__ g, const float* __restrict__ bta,
    __half* __restrict__ out)
{
    int row  = blockIdx.x * 8 + (threadIdx.x >> 5);
    int lane = threadIdx.x & 31;
    const __half2* hp = (const __half2*)(h + (size_t)row * HID);
    const __half2* ap = (const __half2*)(a + (size_t)row * HID);

    float v[8];
    float sum = 0.0f;
#pragma unroll
    for (int j = 0; j < 4; j++) {
        int c2 = lane + 32 * j;
        float2 hv = __half22float2(hp[c2]);
        float2 av = __half22float2(ap[c2]);
        v[2 * j]     = hv.x + av.x;
        v[2 * j + 1] = hv.y + av.y;
        sum += v[2 * j] + v[2 * j + 1];
    }
#pragma unroll
    for (int off = 16; off; off >>= 1) sum += __shfl_xor_sync(0xFFFFFFFFu, sum, off);
    float mu = sum * (1.0f / 256.0f);

    float vs = 0.0f;
#pragma unroll
    for (int j = 0; j < 8; j++) { float d = v[j] - mu; vs += d * d; }
#pragma unroll
    for (int off = 16; off; off >>= 1) vs += __shfl_xor_sync(0xFFFFFFFFu, vs, off);
    float rs = rsqrtf(vs * (1.0f / 256.0f) + 1e-5f);

    __half2* op = (__half2*)(out + (size_t)row * HID);
#pragma unroll
    for (int j = 0; j < 4; j++) {
        int c2 = lane + 32 * j;
        float o0 = (v[2 * j]     - mu) * rs * g[c2 * 2]     + bta[c2 * 2];
        float o1 = (v[2 * j + 1] - mu) * rs * g[c2 * 2 + 1] + bta[c2 * 2 + 1];
        op[c2] = __floats2half2_rn(o0, o1);
    }
}

// ---------------- final: gcn3 mix + pooling ----------------
__global__ __launch_bounds__(256) void k_final(
    const __half* __restrict__ T3, const float* __restrict__ b3,
    float* __restrict__ out)
{
    __shared__ float red[12][8];
    __shared__ float sw[12];
    int b = blockIdx.x, f = threadIdx.x;
    int lane = f & 31, wid = f >> 5;

    float t[LEADS];
#pragma unroll
    for (int j = 0; j < LEADS; j++)
        t[j] = __half2float(T3[((size_t)b * LEADS + j) * HID + f]);

    float bias = b3[f];
    float h3[LEADS];
#pragma unroll
    for (int i = 0; i < LEADS; i++) {
        float acc = bias;
#pragma unroll
        for (int j = 0; j < LEADS; j++) acc += g_A[i * 12 + j] * t[j];
        h3[i] = acc;
    }

#pragma unroll
    for (int i = 0; i < LEADS; i++) {
        float s = h3[i];
#pragma unroll
        for (int off = 16; off; off >>= 1) s += __shfl_xor_sync(0xFFFFFFFFu, s, off);
        if (lane == 0) red[i][wid] = s;
    }
    __syncthreads();
    if (f < 12) {
        float s = 0.0f;
        for (int w = 0; w < 8; w++) s += red[f][w];
        sw[f] = s * (1.0f / 256.0f);
    }
    __syncthreads();
    if (f == 0) {
        float mx = -1e30f;
        for (int i = 0; i < 12; i++) mx = fmaxf(mx, sw[i]);
        float e[12], sum = 0.0f;
        for (int i = 0; i < 12; i++) { e[i] = expf(sw[i] - mx); sum += e[i]; }
        float inv = 1.0f / sum;
        for (int i = 0; i < 12; i++) sw[i] = e[i] * inv;
    }
    __syncthreads();

    float ws = 0.0f, mx = -1e30f;
#pragma unroll
    for (int i = 0; i < LEADS; i++) {
        ws += h3[i] * sw[i];
        mx = fmaxf(mx, h3[i]);
    }
    out[(size_t)b * 512 + f]       = ws;
    out[(size_t)b * 512 + 256 + f] = mx;
}

// ---------------- launcher ----------------
extern "C" void kernel_launch(void* const* d_in, const int* in_sizes, int n_in,
                              void* d_out, int out_size)
{
    const float* x    = (const float*)d_in[0];
    const float* W1   = (const float*)d_in[1];
    const float* b1   = (const float*)d_in[2];
    const float* W2   = (const float*)d_in[3];
    const float* b2   = (const float*)d_in[4];
    const float* W3   = (const float*)d_in[5];
    const float* b3   = (const float*)d_in[6];
    const float* inW  = (const float*)d_in[7];
    const float* inB  = (const float*)d_in[8];
    const float* outW = (const float*)d_in[9];
    const float* outB = (const float*)d_in[10];
    const float* lng  = (const float*)d_in[11];
    const float* lnb  = (const float*)d_in[12];
    float* out = (float*)d_out;

    __half *bufQ, *buf1, *buf2, *buf3;
    cudaGetSymbolAddress((void**)&bufQ, g_qkv);
    cudaGetSymbolAddress((void**)&buf1, g_buf1);
    cudaGetSymbolAddress((void**)&buf2, g_buf2);
    cudaGetSymbolAddress((void**)&buf3, g_buf3);

    __half *w1, *w2, *w3, *iw, *ow;
    cudaGetSymbolAddress((void**)&w1, g_W1);
    cudaGetSymbolAddress((void**)&w2, g_W2);
    cudaGetSymbolAddress((void**)&w3, g_W3);
    cudaGetSymbolAddress((void**)&iw, g_Iw);
    cudaGetSymbolAddress((void**)&ow, g_Ow);

    cudaFuncSetAttribute(k_hgemm<false>, cudaFuncAttributeMaxDynamicSharedMemorySize, SMEM_BYTES);
    cudaFuncSetAttribute(k_hgemm<true>,  cudaFuncAttributeMaxDynamicSharedMemorySize, SMEM_BYTES);

    __half* x16 = bufQ;

    // 1: fused prep
    k_prep<<<PREP_BLOCKS, 256>>>(x, W1, W2, W3, inW, outW, x16);

    dim3 gH(2, MROWS / 256);   // N=256
    dim3 gQ(6, MROWS / 256);   // N=768

    // 2: gcn1 GEMM; 3: mix
    k_hgemm<false><<<gH, 256, SMEM_BYTES>>>(x16, w1, nullptr, buf1, FIN, HID);
    k_mix<true><<<B_SZ / 2, 256>>>(buf1, b1, buf2);

    // 4: gcn2 GEMM; 5: mix
    k_hgemm<false><<<gH, 256, SMEM_BYTES>>>(buf2, w2, nullptr, buf1, HID, HID);
    k_mix<true><<<B_SZ / 2, 256>>>(buf1, b2, buf3);     // buf3 = h2 (residual)

    // 6: qkv GEMM
    k_hgemm<true><<<gQ, 256, SMEM_BYTES>>>(buf3, iw, inB, bufQ, HID, E3);

    // 7: attention
    k_attn<<<B_SZ, 128>>>(bufQ, buf1);

    // 8: out_proj GEMM
    k_hgemm<true><<<gH, 256, SMEM_BYTES>>>(buf1, ow, outB, buf2, HID, HID);

    // 9: residual + LN
    k_ln<<<MROWS / 8, 256>>>(buf3, buf2, lng, lnb, buf1);

    // 10: gcn3 GEMM
    k_hgemm<false><<<gH, 256, SMEM_BYTES>>>(buf1, w3, nullptr, buf2, HID, HID);

    // 11: pooling
    k_final<<<B_SZ, 256>>>(buf2, b3, out);
}

// round 12
// speedup vs baseline: 1.4968x; 1.1268x over previous
#include <cuda_runtime.h>
#include <cuda_fp16.h>
#include <cstdint>
#include <math.h>

#define B_SZ   8192
#define LEADS  12
#define FIN    512
#define HID    256
#define E3     768
#define MROWS  (B_SZ * LEADS)   // 98304

// ---------------- static scratch ----------------
__device__ float g_A[LEADS * LEADS];
__device__ __half g_qkv[(size_t)MROWS * E3];   // also reused as x16 before qkv
__device__ __half g_buf1[(size_t)MROWS * HID];
__device__ __half g_buf2[(size_t)MROWS * HID];
__device__ __half g_buf3[(size_t)MROWS * HID];

__device__ __half g_W1[HID * FIN];
__device__ __half g_W2[HID * HID];
__device__ __half g_W3[HID * HID];
__device__ __half g_Iw[E3 * HID];
__device__ __half g_Ow[HID * HID];

// ---------------- helpers ----------------
__device__ __forceinline__ uint32_t smem_u32(const void* p) {
    uint32_t a;
    asm("{ .reg .u64 t; cvta.to.shared.u64 t, %1; cvt.u32.u64 %0, t; }" : "=r"(a) : "l"(p));
    return a;
}
__device__ __forceinline__ void ldsm4(uint32_t& r0, uint32_t& r1, uint32_t& r2, uint32_t& r3,
                                      uint32_t a) {
    asm volatile("ldmatrix.sync.aligned.m8n8.x4.shared.b16 {%0,%1,%2,%3}, [%4];"
                 : "=r"(r0), "=r"(r1), "=r"(r2), "=r"(r3) : "r"(a));
}
__device__ __forceinline__ void ldsm4t(uint32_t& r0, uint32_t& r1, uint32_t& r2, uint32_t& r3,
                                       uint32_t a) {
    asm volatile("ldmatrix.sync.aligned.m8n8.x4.trans.shared.b16 {%0,%1,%2,%3}, [%4];"
                 : "=r"(r0), "=r"(r1), "=r"(r2), "=r"(r3) : "r"(a));
}
__device__ __forceinline__ void mma16816(float* c, const uint32_t* a, const uint32_t* b) {
    asm volatile("mma.sync.aligned.m16n8k16.row.col.f32.f16.f16.f32 "
                 "{%0,%1,%2,%3}, {%4,%5,%6,%7}, {%8,%9}, {%0,%1,%2,%3};"
                 : "+f"(c[0]), "+f"(c[1]), "+f"(c[2]), "+f"(c[3])
                 : "r"(a[0]), "r"(a[1]), "r"(a[2]), "r"(a[3]), "r"(b[0]), "r"(b[1]));
}
__device__ __forceinline__ void cp16(uint32_t d, const void* g) {
    asm volatile("cp.async.ca.shared.global [%0], [%1], 16;" :: "r"(d), "l"(g));
}
#define CP_COMMIT  asm volatile("cp.async.commit_group;" ::: "memory")
#define CP_WAIT(n) asm volatile("cp.async.wait_group %0;" :: "n"(n) : "memory")

// ---------------- fused prep ----------------
#define PREP_X4   12582912
#define PREP_W1   (PREP_X4 + 131072)
#define PREP_W2   (PREP_W1 + 65536)
#define PREP_W3   (PREP_W2 + 65536)
#define PREP_IW   (PREP_W3 + 196608)
#define PREP_OW   (PREP_IW + 65536)
#define PREP_BLOCKS  (PREP_OW / 256)

__global__ void k_prep(const float* __restrict__ x,  const float* __restrict__ W1,
                       const float* __restrict__ W2, const float* __restrict__ W3,
                       const float* __restrict__ inW, const float* __restrict__ outW,
                       __half* __restrict__ x16)
{
    size_t gid = (size_t)blockIdx.x * blockDim.x + threadIdx.x;
    if (gid == 0) {
        const int ci[18] = {0,0,1,0,1,2,0,1,1,2,6,7,8,9,10,0,1,2};
        const int cj[18] = {1,2,2,3,3,3,4,4,5,5,7,8,9,10,11,6,9,11};
        float A[12][12];
        for (int i = 0; i < 12; i++)
            for (int j = 0; j < 12; j++) A[i][j] = (i == j) ? 1.0f : 0.0f;
        for (int e = 0; e < 18; e++) { A[ci[e]][cj[e]] = 1.0f; A[cj[e]][ci[e]] = 1.0f; }
        float dinv[12];
        for (int i = 0; i < 12; i++) {
            float s = 0.0f;
            for (int j = 0; j < 12; j++) s += A[i][j];
            dinv[i] = 1.0f / sqrtf(s);
        }
        for (int i = 0; i < 12; i++)
            for (int j = 0; j < 12; j++) g_A[i * 12 + j] = dinv[i] * A[i][j] * dinv[j];
    }
    if (gid < PREP_X4) {
        float4 v = ((const float4*)x)[gid];
        ((__half2*)x16)[gid * 2]     = __floats2half2_rn(v.x, v.y);
        ((__half2*)x16)[gid * 2 + 1] = __floats2half2_rn(v.z, v.w);
        return;
    }
    if (gid < PREP_W1) {
        size_t l = gid - PREP_X4;
        int k = (int)(l >> 8), n = (int)(l & 255);
        g_W1[n * FIN + k] = __float2half_rn(W1[l]);
        return;
    }
    if (gid < PREP_W2) {
        size_t l = gid - PREP_W1;
        int k = (int)(l >> 8), n = (int)(l & 255);
        g_W2[n * HID + k] = __float2half_rn(W2[l]);
        return;
    }
    if (gid < PREP_W3) {
        size_t l = gid - PREP_W2;
        int k = (int)(l >> 8), n = (int)(l & 255);
        g_W3[n * HID + k] = __float2half_rn(W3[l]);
        return;
    }
    if (gid < PREP_IW) {
        size_t l = gid - PREP_W3;
        g_Iw[l] = __float2half_rn(inW[l]);
        return;
    }
    if (gid < PREP_OW) {
        size_t l = gid - PREP_IW;
        g_Ow[l] = __float2half_rn(outW[l]);
        return;
    }
}

// ---------------- GEMM core (R8/R11 geometry, unchanged) ----------------
#define SROW    72
#define B_OFF_H (256 * SROW)
#define STAGE_H (384 * SROW)
#define STAGE_B (STAGE_H * 2)
#define NSTAGE  3
#define SMEM_BYTES (NSTAGE * STAGE_B)

struct GemmCtx {
    int lane, wm, wn;
    int arow, akblk, bn, bkblk, bntoff;
};

__device__ __forceinline__ GemmCtx make_ctx(int tid) {
    GemmCtx g;
    g.lane = tid & 31;
    int w = tid >> 5;
    g.wm = w >> 1;
    g.wn = w & 1;
    g.arow  = (g.lane & 7) | (((g.lane >> 3) & 1) << 3);
    g.akblk = (g.lane >> 4) & 1;
    int bwhich = g.lane >> 3;
    g.bn     = g.lane & 7;
    g.bkblk  = bwhich & 1;
    g.bntoff = bwhich >> 1;
    return g;
}

__device__ __forceinline__ void load_frags(const GemmCtx& g, uint32_t so, int ks,
                                           uint32_t ah[4][4], uint32_t bh[4][4]) {
#pragma unroll
    for (int mt = 0; mt < 4; mt++) {
        uint32_t aoff = so + ((g.wm * 64 + mt * 16 + g.arow) * SROW + ks * 16 + g.akblk * 8) * 2;
        ldsm4(ah[mt][0], ah[mt][1], ah[mt][2], ah[mt][3], aoff);
    }
#pragma unroll
    for (int p = 0; p < 4; p++) {
        int nt = p * 2 + g.bntoff;
        uint32_t boff = so + (B_OFF_H + (g.wn * 64 + nt * 8 + g.bn) * SROW + ks * 16 + g.bkblk * 8) * 2;
        ldsm4(bh[p][0], bh[p][1], bh[p][2], bh[p][3], boff);
    }
}

__device__ __forceinline__ void do_mmas(const uint32_t ah[4][4], const uint32_t bh[4][4],
                                        float c[4][8][4]) {
#pragma unroll
    for (int mt = 0; mt < 4; mt++)
#pragma unroll
        for (int p = 0; p < 4; p++)
#pragma unroll
            for (int h = 0; h < 2; h++)
                mma16816(c[mt][p * 2 + h], ah[mt], &bh[p][h * 2]);
}

template <bool BIAS>
__global__ __launch_bounds__(256, 1) void k_hgemm(
    const __half* __restrict__ A,
    const __half* __restrict__ B,
    const float* __restrict__ bias,
    __half* __restrict__ C,
    int K, int N)
{
    extern __shared__ __half sm[];
    const int tid  = threadIdx.x;
    const int row0 = blockIdx.y * 256;
    const int col0 = blockIdx.x * 128;
    const int NC   = K >> 6;
    const uint32_t sbase = smem_u32(sm);
    GemmCtx g = make_ctx(tid);

    float c[4][8][4];
#pragma unroll
    for (int i = 0; i < 4; i++)
#pragma unroll
        for (int j = 0; j < 8; j++)
#pragma unroll
            for (int q = 0; q < 4; q++) c[i][j][q] = 0.0f;

    const int rr = tid >> 3;
    const int qq = (tid & 7) * 8;
    const __half* Ab = A + (size_t)(row0 + rr) * K + qq;
    const __half* Bb = B + (size_t)(col0 + rr) * K + qq;
    const uint32_t doff = (rr * SROW + qq) * 2;

    auto cpa = [&](int cc) {
        uint32_t st = sbase + (cc % 3) * STAGE_B + doff;
        const __half* Ac = Ab + cc * 64;
        const __half* Bc = Bb + cc * 64;
#pragma unroll
        for (int u = 0; u < 8; u++)
            cp16(st + u * 32 * SROW * 2, Ac + (size_t)(u * 32) * K);
#pragma unroll
        for (int u = 0; u < 4; u++)
            cp16(st + (B_OFF_H + u * 32 * SROW) * 2, Bc + (size_t)(u * 32) * K);
    };

    int npre = NC < 2 ? NC : 2;
    for (int s = 0; s < npre; s++) { cpa(s); CP_COMMIT; }

    uint32_t ah[2][4][4], bh[2][4][4];

    for (int cc = 0; cc < NC; cc++) {
        if (cc + 1 < NC) CP_WAIT(1); else CP_WAIT(0);
        __syncthreads();
        if (cc + 2 < NC) { cpa(cc + 2); CP_COMMIT; }

        uint32_t so = sbase + (cc % 3) * STAGE_B;
        load_frags(g, so, 0, ah[0], bh[0]);
#pragma unroll
        for (int ks = 0; ks < 4; ks++) {
            int cur = ks & 1;
            if (ks < 3) load_frags(g, so, ks + 1, ah[cur ^ 1], bh[cur ^ 1]);
            do_mmas(ah[cur], bh[cur], c);
        }
        __syncthreads();
    }

#pragma unroll
    for (int mt = 0; mt < 4; mt++) {
        int row = row0 + g.wm * 64 + mt * 16 + (g.lane >> 2);
#pragma unroll
        for (int n8 = 0; n8 < 8; n8++) {
            int col = col0 + g.wn * 64 + n8 * 8 + (g.lane & 3) * 2;
            float b0 = 0.0f, b1 = 0.0f;
            if (BIAS) { b0 = bias[col]; b1 = bias[col + 1]; }
            __half2 o0 = __floats2half2_rn(c[mt][n8][0] + b0, c[mt][n8][1] + b1);
            __half2 o1 = __floats2half2_rn(c[mt][n8][2] + b0, c[mt][n8][3] + b1);
            *(__half2*)(C + (size_t)row * N + col)       = o0;
            *(__half2*)(C + (size_t)(row + 8) * N + col) = o1;
        }
    }
}

// ---------------- lead-mix ----------------
template <bool RELU>
__global__ __launch_bounds__(256) void k_mix(
    const __half* __restrict__ T, const float* __restrict__ bias,
    __half* __restrict__ out)
{
    int b  = blockIdx.x * 2 + (threadIdx.x >> 7);
    int f2 = threadIdx.x & 127;
    const __half2* Tb = (const __half2*)(T + (size_t)b * LEADS * HID) + f2;
    float2 t[LEADS];
#pragma unroll
    for (int j = 0; j < LEADS; j++) t[j] = __half22float2(Tb[j * 128]);
    float b0 = bias[f2 * 2], b1 = bias[f2 * 2 + 1];
    __half2* Ob = (__half2*)(out + (size_t)b * LEADS * HID) + f2;
#pragma unroll
    for (int i = 0; i < LEADS; i++) {
        float ax = b0, ay = b1;
#pragma unroll
        for (int j = 0; j < LEADS; j++) {
            float w = g_A[i * 12 + j];
            ax += w * t[j].x; ay += w * t[j].y;
        }
        if (RELU) { ax = fmaxf(ax, 0.0f); ay = fmaxf(ay, 0.0f); }
        Ob[i * 128] = __floats2half2_rn(ax, ay);
    }
}

// ---------------- attention via mma (per block: 1 batch, warp = head) ----------------
#define SA 72
#define PA 24

__global__ __launch_bounds__(128) void k_attn(const __half* __restrict__ qkv,
                                              __half* __restrict__ o)
{
    __shared__ __align__(16) __half sQ[4][16 * SA];
    __shared__ __align__(16) __half sK[4][16 * SA];
    __shared__ __align__(16) __half sV[4][16 * SA];
    __shared__ __align__(16) __half sP[4][16 * PA];
    __shared__ float ss[4][12][12];

    int b    = blockIdx.x;
    int w    = threadIdx.x >> 5;
    int lane = threadIdx.x & 31;
    const __half* base = qkv + (size_t)b * LEADS * E3;

    // zero pad rows 12-15 of Q,K,V and all of P
    uint4 z = make_uint4(0, 0, 0, 0);
    for (int i = lane; i < 36; i += 32) {       // 4 rows * 72 halves = 36 uint4
        ((uint4*)(sQ[w] + 12 * SA))[i] = z;
        ((uint4*)(sK[w] + 12 * SA))[i] = z;
        ((uint4*)(sV[w] + 12 * SA))[i] = z;
    }
    for (int i = lane; i < 48; i += 32)         // 16 * 24 halves = 48 uint4
        ((uint4*)sP[w])[i] = z;

    // load q,k,v (12 rows x 64 halves each), uint4 per lane-iter
#pragma unroll
    for (int i = 0; i < 3; i++) {
        int u = lane + 32 * i;
        int s = u >> 3, ch = (u & 7) * 8;
        *(uint4*)(sQ[w] + s * SA + ch) = *(const uint4*)(base + s * E3 +       w * 64 + ch);
        *(uint4*)(sK[w] + s * SA + ch) = *(const uint4*)(base + s * E3 + 256 + w * 64 + ch);
        *(uint4*)(sV[w] + s * SA + ch) = *(const uint4*)(base + s * E3 + 512 + w * 64 + ch);
    }
    __syncwarp();

    const int arow  = (lane & 7) | (((lane >> 3) & 1) << 3);   // A / trans-B row pattern
    const int akblk = (lane >> 4) & 1;
    const int brow  = (lane & 7) + ((lane >> 4) & 1) * 8;      // non-trans B row pattern
    const int bkblk = (lane >> 3) & 1;
    const int r     = lane >> 2;
    const int cb    = (lane & 3) * 2;

    // scores: S(16x16) = Q(16x64) @ K^T, fp32 accum
    float cs[2][4] = {};
#pragma unroll
    for (int kc = 0; kc < 4; kc++) {
        uint32_t qa[4], kb[4];
        ldsm4(qa[0], qa[1], qa[2], qa[3],
              smem_u32(sQ[w] + arow * SA + kc * 16 + akblk * 8));
        ldsm4(kb[0], kb[1], kb[2], kb[3],
              smem_u32(sK[w] + brow * SA + kc * 16 + bkblk * 8));
        mma16816(cs[0], qa, &kb[0]);
        mma16816(cs[1], qa, &kb[2]);
    }
#pragma unroll
    for (int nt = 0; nt < 2; nt++) {
        int col = nt * 8 + cb;
        if (col < 12) {
            if (r < 12) {
                ss[w][r][col]     = cs[nt][0] * 0.125f;
                ss[w][r][col + 1] = cs[nt][1] * 0.125f;
            }
            if (r + 8 < 12) {
                ss[w][r + 8][col]     = cs[nt][2] * 0.125f;
                ss[w][r + 8][col + 1] = cs[nt][3] * 0.125f;
            }
        }
    }
    __syncwarp();

    // softmax over t (rows of ss), probs -> sP fp16
    if (lane < 12) {
        float mx = -1e30f;
        for (int t = 0; t < 12; t++) mx = fmaxf(mx, ss[w][lane][t]);
        float e[12], sum = 0.0f;
        for (int t = 0; t < 12; t++) { e[t] = expf(ss[w][lane][t] - mx); sum += e[t]; }
        float inv = 1.0f / sum;
        for (int t = 0; t < 12; t++) sP[w][lane * PA + t] = __float2half_rn(e[t] * inv);
    }
    __syncwarp();

    // output: O(16x64) = P(16x16) @ V(16x64); V is [t][d] -> trans ldsm for B
    uint32_t pa[4];
    ldsm4(pa[0], pa[1], pa[2], pa[3], smem_u32(sP[w] + arow * PA + akblk * 8));
    float co[8][4] = {};
#pragma unroll
    for (int g4 = 0; g4 < 4; g4++) {
        uint32_t vb[4];
        ldsm4t(vb[0], vb[1], vb[2], vb[3],
               smem_u32(sV[w] + arow * SA + (lane >> 4) * 8 + g4 * 16));
        mma16816(co[g4 * 2],     pa, &vb[0]);
        mma16816(co[g4 * 2 + 1], pa, &vb[2]);
    }

    __half* ob = o + ((size_t)b * LEADS) * HID + w * 64;
#pragma unroll
    for (int nt = 0; nt < 8; nt++) {
        int d = nt * 8 + cb;
        if (r < 12)
            *(__half2*)(ob + (size_t)r * HID + d) = __floats2half2_rn(co[nt][0], co[nt][1]);
        if (r + 8 < 12)
            *(__half2*)(ob + (size_t)(r + 8) * HID + d) = __floats2half2_rn(co[nt][2], co[nt][3]);
    }
}

// ---------------- residual + LayerNorm ----------------
__global__ __launch_bounds__(256) void k_ln(
    const __half* __restrict__ h, const __half* __restrict__ a,
    const float* __restrict__ g, const float* __restrict__ bta,
    __half* __restrict__ out)
{
    int row  = blockIdx.x * 8 + (threadIdx.x >> 5);
    int lane = threadIdx.x & 31;
    const __half2* hp = (const __half2*)(h + (size_t)row * HID);
    const __half2* ap = (const __half2*)(a + (size_t)row * HID);

    float v[8];
    float sum = 0.0f;
#pragma unroll
    for (int j = 0; j < 4; j++) {
        int c2 = lane + 32 * j;
        float2 hv = __half22float2(hp[c2]);
        float2 av = __half22float2(ap[c2]);
        v[2 * j]     = hv.x + av.x;
        v[2 * j + 1] = hv.y + av.y;
        sum += v[2 * j] + v[2 * j + 1];
    }
#pragma unroll
    for (int off = 16; off; off >>= 1) sum += __shfl_xor_sync(0xFFFFFFFFu, sum, off);
    float mu = sum * (1.0f / 256.0f);

    float vs = 0.0f;
#pragma unroll
    for (int j = 0; j < 8; j++) { float d = v[j] - mu; vs += d * d; }
#pragma unroll
    for (int off = 16; off; off >>= 1) vs += __shfl_xor_sync(0xFFFFFFFFu, vs, off);
    float rs = rsqrtf(vs * (1.0f / 256.0f) + 1e-5f);

    __half2* op = (__half2*)(out + (size_t)row * HID);
#pragma unroll
    for (int j = 0; j < 4; j++) {
        int c2 = lane + 32 * j;
        float o0 = (v[2 * j]     - mu) * rs * g[c2 * 2]     + bta[c2 * 2];
        float o1 = (v[2 * j + 1] - mu) * rs * g[c2 * 2 + 1] + bta[c2 * 2 + 1];
        op[c2] = __floats2half2_rn(o0, o1);
    }
}

// ---------------- final: gcn3 mix + pooling ----------------
__global__ __launch_bounds__(256) void k_final(
    const __half* __restrict__ T3, const float* __restrict__ b3,
    float* __restrict__ out)
{
    __shared__ float red[12][8];
    __shared__ float sw[12];
    int b = blockIdx.x, f = threadIdx.x;
    int lane = f & 31, wid = f >> 5;

    float t[LEADS];
#pragma unroll
    for (int j = 0; j < LEADS; j++)
        t[j] = __half2float(T3[((size_t)b * LEADS + j) * HID + f]);

    float bias = b3[f];
    float h3[LEADS];
#pragma unroll
    for (int i = 0; i < LEADS; i++) {
        float acc = bias;
#pragma unroll
        for (int j = 0; j < LEADS; j++) acc += g_A[i * 12 + j] * t[j];
        h3[i] = acc;
    }

#pragma unroll
    for (int i = 0; i < LEADS; i++) {
        float s = h3[i];
#pragma unroll
        for (int off = 16; off; off >>= 1) s += __shfl_xor_sync(0xFFFFFFFFu, s, off);
        if (lane == 0) red[i][wid] = s;
    }
    __syncthreads();
    if (f < 12) {
        float s = 0.0f;
        for (int w = 0; w < 8; w++) s += red[f][w];
        sw[f] = s * (1.0f / 256.0f);
    }
    __syncthreads();
    if (f == 0) {
        float mx = -1e30f;
        for (int i = 0; i < 12; i++) mx = fmaxf(mx, sw[i]);
        float e[12], sum = 0.0f;
        for (int i = 0; i < 12; i++) { e[i] = expf(sw[i] - mx); sum += e[i]; }
        float inv = 1.0f / sum;
        for (int i = 0; i < 12; i++) sw[i] = e[i] * inv;
    }
    __syncthreads();

    float ws = 0.0f, mx = -1e30f;
#pragma unroll
    for (int i = 0; i < LEADS; i++) {
        ws += h3[i] * sw[i];
        mx = fmaxf(mx, h3[i]);
    }
    out[(size_t)b * 512 + f]       = ws;
    out[(size_t)b * 512 + 256 + f] = mx;
}

// ---------------- launcher ----------------
extern "C" void kernel_launch(void* const* d_in, const int* in_sizes, int n_in,
                              void* d_out, int out_size)
{
    const float* x    = (const float*)d_in[0];
    const float* W1   = (const float*)d_in[1];
    const float* b1   = (const float*)d_in[2];
    const float* W2   = (const float*)d_in[3];
    const float* b2   = (const float*)d_in[4];
    const float* W3   = (const float*)d_in[5];
    const float* b3   = (const float*)d_in[6];
    const float* inW  = (const float*)d_in[7];
    const float* inB  = (const float*)d_in[8];
    const float* outW = (const float*)d_in[9];
    const float* outB = (const float*)d_in[10];
    const float* lng  = (const float*)d_in[11];
    const float* lnb  = (const float*)d_in[12];
    float* out = (float*)d_out;

    __half *bufQ, *buf1, *buf2, *buf3;
    cudaGetSymbolAddress((void**)&bufQ, g_qkv);
    cudaGetSymbolAddress((void**)&buf1, g_buf1);
    cudaGetSymbolAddress((void**)&buf2, g_buf2);
    cudaGetSymbolAddress((void**)&buf3, g_buf3);

    __half *w1, *w2, *w3, *iw, *ow;
    cudaGetSymbolAddress((void**)&w1, g_W1);
    cudaGetSymbolAddress((void**)&w2, g_W2);
    cudaGetSymbolAddress((void**)&w3, g_W3);
    cudaGetSymbolAddress((void**)&iw, g_Iw);
    cudaGetSymbolAddress((void**)&ow, g_Ow);

    cudaFuncSetAttribute(k_hgemm<false>, cudaFuncAttributeMaxDynamicSharedMemorySize, SMEM_BYTES);
    cudaFuncSetAttribute(k_hgemm<true>,  cudaFuncAttributeMaxDynamicSharedMemorySize, SMEM_BYTES);

    __half* x16 = bufQ;

    // 1: fused prep
    k_prep<<<PREP_BLOCKS, 256>>>(x, W1, W2, W3, inW, outW, x16);

    dim3 gH(2, MROWS / 256);   // N=256
    dim3 gQ(6, MROWS / 256);   // N=768

    // 2: gcn1 GEMM; 3: mix
    k_hgemm<false><<<gH, 256, SMEM_BYTES>>>(x16, w1, nullptr, buf1, FIN, HID);
    k_mix<true><<<B_SZ / 2, 256>>>(buf1, b1, buf2);

    // 4: gcn2 GEMM; 5: mix
    k_hgemm<false><<<gH, 256, SMEM_BYTES>>>(buf2, w2, nullptr, buf1, HID, HID);
    k_mix<true><<<B_SZ / 2, 256>>>(buf1, b2, buf3);     // buf3 = h2 (residual)

    // 6: qkv GEMM
    k_hgemm<true><<<gQ, 256, SMEM_BYTES>>>(buf3, iw, inB, bufQ, HID, E3);

    // 7: attention
    k_attn<<<B_SZ, 128>>>(bufQ, buf1);

    // 8: out_proj GEMM
    k_hgemm<true><<<gH, 256, SMEM_BYTES>>>(buf1, ow, outB, buf2, HID, HID);

    // 9: residual + LN
    k_ln<<<MROWS / 8, 256>>>(buf3, buf2, lng, lnb, buf1);

    // 10: gcn3 GEMM
    k_hgemm<false><<<gH, 256, SMEM_BYTES>>>(buf1, w3, nullptr, buf2, HID, HID);

    // 11: pooling
    k_final<<<B_SZ, 256>>>(buf2, b3, out);
}